// round 10
// baseline (speedup 1.0000x reference)
#include <cuda_runtime.h>
#include <math.h>
#include <stdint.h>

#define NB 48
#define SS 1024
#define DD 128
#define DKK 64

// scratch (static device globals: allocation-free per harness rules)
__device__ float g_Q[NB * SS * DKK];   // tf32-rounded projections
__device__ float g_K[NB * SS * DKK];
__device__ float g_Z[NB];
__device__ int   g_cnt[NB];
__device__ int   g_wready;             // W-split done counter (replay-sticky)
// W split into tf32 hi/lo, TRANSPOSED to [n][k] (n: 0..63 Wq, 64..127 Wk)
__device__ uint32_t g_WhT[DD * DD];
__device__ uint32_t g_WlT[DD * DD];

__device__ __forceinline__ uint32_t f2tf32(float v) {
    uint32_t r;
    asm("cvt.rna.tf32.f32 %0, %1;" : "=r"(r) : "f"(v));
    return r;
}

// ---------------------------------------------------------------------------
// Kernel 1: fused Q|K projection, 2-term tf32: C = Ah*Wh + Ah*Wl.
// Setup is MERGED: CTAs 0..7 each split 1/8 of W into g_WhT/g_WlT and bump
// g_wready; all CTAs spin until g_wready >= 8 before staging W. Replay-safe:
// on graph replays the counter stays >= 8 (spin passes immediately) and CTAs
// 0..7 rewrite bit-identical values (W is the same input every call).
// __launch_bounds__(256,3): 384 CTAs fit in ONE wave (3/SM * 148 = 444).
// Block 0 zeroes g_Z / g_cnt (visible to score across kernel boundary).
// Outputs tf32-rounded so score stages them as a pure cp.async byte copy.
// ---------------------------------------------------------------------------
#define PROJ_SMEM (3 * 128 * 36 * 4)

__global__ __launch_bounds__(256, 3) void proj_kernel(
    const float* __restrict__ A,
    const float* __restrict__ Wq,
    const float* __restrict__ Wk)
{
    const int tid  = threadIdx.x;
    const int lane = tid & 31, warp = tid >> 5;

    if (blockIdx.x == 0 && tid < NB) {
        g_Z[tid] = 0.f;
        g_cnt[tid] = 0;
    }

    // ---- distributed W split (CTAs 0..7, 2048 elements each) ----
    if (blockIdx.x < 8) {
#pragma unroll
        for (int j = 0; j < 8; j++) {
            int idx = blockIdx.x * 2048 + tid * 8 + j;   // 0..16383
            int k = idx >> 7, n = idx & 127;
            float v = (n < 64) ? Wq[k * DKK + n] : Wk[k * DKK + (n - 64)];
            uint32_t hi = f2tf32(v);
            g_WhT[n * DD + k] = hi;
            g_WlT[n * DD + k] = f2tf32(v - __uint_as_float(hi));
        }
        __threadfence();
        __syncthreads();
        if (tid == 0) atomicAdd(&g_wready, 1);
    }
    // all CTAs wait until the full W split is published
    if (tid == 0) {
        volatile int* vr = &g_wready;
        while (*vr < 8) { }
    }
    __syncthreads();
    __threadfence();   // order: spin-observed flag before W reads below

    extern __shared__ uint32_t smem[];
    uint32_t* sAh = smem;                 // [128][36]
    uint32_t* sWh = sAh + 128 * 36;       // [n][k] transposed
    uint32_t* sWl = sWh + 128 * 36;

    const int rowbase = blockIdx.x * 128;
    const int mrow = (warp & 3) * 32;
    const int ncol = (warp >> 2) * 64;
    const int g  = lane >> 2;
    const int tr = lane & 3;

    float acc[2][8][4];
#pragma unroll
    for (int mt = 0; mt < 2; mt++)
#pragma unroll
        for (int nt = 0; nt < 8; nt++)
#pragma unroll
            for (int r = 0; r < 4; r++) acc[mt][nt][r] = 0.f;

    for (int k0 = 0; k0 < DD; k0 += 32) {
        // stage A chunk 128x32, tf32 hi only, STS.128 (row stride 144B)
#pragma unroll
        for (int it = 0; it < 4; it++) {
            int f = tid + 256 * it;
            int m = f >> 3, k4 = (f & 7) * 4;
            float4 v = *(const float4*)(A + (size_t)(rowbase + m) * DD + k0 + k4);
            uint4 h = make_uint4(f2tf32(v.x), f2tf32(v.y),
                                 f2tf32(v.z), f2tf32(v.w));
            *(uint4*)&sAh[m * 36 + k4] = h;
        }
#pragma unroll
        for (int it = 0; it < 4; it++) {
            int f = tid + 256 * it;
            int n = f >> 3, k4 = (f & 7) * 4;
            *(uint4*)&sWh[n * 36 + k4] = *(const uint4*)(g_WhT + n * DD + k0 + k4);
            *(uint4*)&sWl[n * 36 + k4] = *(const uint4*)(g_WlT + n * DD + k0 + k4);
        }
        __syncthreads();

#pragma unroll
        for (int kc = 0; kc < 4; kc++) {
            const int kk = kc * 8;
            uint32_t ah[2][4];
#pragma unroll
            for (int mt = 0; mt < 2; mt++) {
                int r = mrow + mt * 16 + g;
                ah[mt][0] = sAh[r * 36 + kk + tr];
                ah[mt][1] = sAh[(r + 8) * 36 + kk + tr];
                ah[mt][2] = sAh[r * 36 + kk + tr + 4];
                ah[mt][3] = sAh[(r + 8) * 36 + kk + tr + 4];
            }
#pragma unroll
            for (int nt = 0; nt < 8; nt++) {
                int c = ncol + nt * 8 + g;
                uint32_t bh0 = sWh[c * 36 + kk + tr];
                uint32_t bh1 = sWh[c * 36 + kk + tr + 4];
                uint32_t bl0 = sWl[c * 36 + kk + tr];
                uint32_t bl1 = sWl[c * 36 + kk + tr + 4];
#pragma unroll
                for (int mt = 0; mt < 2; mt++) {
                    asm volatile(
                        "mma.sync.aligned.m16n8k8.row.col.f32.tf32.tf32.f32 "
                        "{%0,%1,%2,%3}, {%4,%5,%6,%7}, {%8,%9}, {%0,%1,%2,%3};"
                        : "+f"(acc[mt][nt][0]), "+f"(acc[mt][nt][1]),
                          "+f"(acc[mt][nt][2]), "+f"(acc[mt][nt][3])
                        : "r"(ah[mt][0]), "r"(ah[mt][1]), "r"(ah[mt][2]), "r"(ah[mt][3]),
                          "r"(bh0), "r"(bh1));
                    asm volatile(
                        "mma.sync.aligned.m16n8k8.row.col.f32.tf32.tf32.f32 "
                        "{%0,%1,%2,%3}, {%4,%5,%6,%7}, {%8,%9}, {%0,%1,%2,%3};"
                        : "+f"(acc[mt][nt][0]), "+f"(acc[mt][nt][1]),
                          "+f"(acc[mt][nt][2]), "+f"(acc[mt][nt][3])
                        : "r"(ah[mt][0]), "r"(ah[mt][1]), "r"(ah[mt][2]), "r"(ah[mt][3]),
                          "r"(bl0), "r"(bl1));
                }
            }
        }
        __syncthreads();
    }

    // store tf32-ROUNDED outputs (score stages them as a raw copy)
#pragma unroll
    for (int mt = 0; mt < 2; mt++) {
        int m0 = rowbase + mrow + mt * 16 + g;
#pragma unroll
        for (int nt = 0; nt < 8; nt++) {
            int c = ncol + nt * 8 + tr * 2;
            float* dst = (c < 64) ? g_Q : g_K;
            int cc = c & 63;
            *(float2*)(dst + (size_t)m0 * DKK + cc) = make_float2(
                __uint_as_float(f2tf32(acc[mt][nt][0])),
                __uint_as_float(f2tf32(acc[mt][nt][1])));
            *(float2*)(dst + (size_t)(m0 + 8) * DKK + cc) = make_float2(
                __uint_as_float(f2tf32(acc[mt][nt][2])),
                __uint_as_float(f2tf32(acc[mt][nt][3])));
        }
    }
}

// ---------------------------------------------------------------------------
// Kernel 2: score tile + self-normalizing epilogue (R9 structure).
// Epilogue transform minimized to 6 inst/elem with fused exp2 constants:
//   t = ex2(x*2log2e); r = rcp(t+1); u = ex2(-20log2e * r)
// (same 3 MUFU ops and error structure as before; two FMULs fewer).
// Saturation: x->+inf => t=inf, r=0, u=1; x->-inf => t=0, r=1, u=e^-20.
// ---------------------------------------------------------------------------
#define SCORE_SMEM (2 * 128 * 68 * 4)

__device__ __forceinline__ float uexp(float x) {
    float t, r, u;
    asm("ex2.approx.f32 %0, %1;" : "=f"(t) : "f"(x * 2.8853900817779268f));
    asm("rcp.approx.f32 %0, %1;" : "=f"(r) : "f"(t + 1.0f));
    asm("ex2.approx.f32 %0, %1;" : "=f"(u) : "f"(r * -28.853900817779268f));
    return u;
}

__global__ __launch_bounds__(256, 3) void score_kernel(float* __restrict__ out)
{
    extern __shared__ uint32_t ssm[];
    uint32_t* sQ = ssm;                // [128][68]
    uint32_t* sK = ssm + 128 * 68;
    __shared__ float swarp[8];
    __shared__ float sinv;

    const int tid  = threadIdx.x;
    const int lane = tid & 31, warp = tid >> 5;
    const int bz    = blockIdx.x >> 6;
    const int tile  = blockIdx.x & 63;
    const int qbase = (tile >> 3) * 128;
    const int sbase = (tile & 7) * 128;

    const float* Qb = g_Q + (size_t)bz * SS * DKK + (size_t)qbase * DKK;
    const float* Kb = g_K + (size_t)bz * SS * DKK + (size_t)sbase * DKK;

    const int mrow = (warp & 3) * 32;
    const int ncol = (warp >> 2) * 64;
    const int g  = lane >> 2;
    const int tr = lane & 3;

    // stage full 128x64 Q and K tiles via cp.async (pure copy, MLP=16)
#pragma unroll
    for (int it = 0; it < 8; it++) {
        int f = tid + 256 * it;            // 0..2047
        int m = f >> 4, k4 = (f & 15) * 4;
        uint32_t dq = (uint32_t)__cvta_generic_to_shared(&sQ[m * 68 + k4]);
        asm volatile("cp.async.cg.shared.global [%0], [%1], 16;"
                     :: "r"(dq), "l"(Qb + m * DKK + k4));
        uint32_t dk = (uint32_t)__cvta_generic_to_shared(&sK[m * 68 + k4]);
        asm volatile("cp.async.cg.shared.global [%0], [%1], 16;"
                     :: "r"(dk), "l"(Kb + m * DKK + k4));
    }
    asm volatile("cp.async.commit_group;");

    float acc[2][8][4];
#pragma unroll
    for (int mt = 0; mt < 2; mt++)
#pragma unroll
        for (int nt = 0; nt < 8; nt++)
#pragma unroll
            for (int r = 0; r < 4; r++) acc[mt][nt][r] = 0.f;

    asm volatile("cp.async.wait_group 0;");
    __syncthreads();

#pragma unroll
    for (int kc = 0; kc < 8; kc++) {
        const int k0 = kc * 8;
        uint32_t a[2][4];
#pragma unroll
        for (int mt = 0; mt < 2; mt++) {
            int r = mrow + mt * 16 + g;
            a[mt][0] = sQ[r * 68 + k0 + tr];
            a[mt][1] = sQ[(r + 8) * 68 + k0 + tr];
            a[mt][2] = sQ[r * 68 + k0 + tr + 4];
            a[mt][3] = sQ[(r + 8) * 68 + k0 + tr + 4];
        }
#pragma unroll
        for (int nt = 0; nt < 8; nt++) {
            int c = ncol + nt * 8 + g;
            uint32_t b0 = sK[c * 68 + k0 + tr];
            uint32_t b1 = sK[c * 68 + k0 + tr + 4];
#pragma unroll
            for (int mt = 0; mt < 2; mt++) {
                asm volatile(
                    "mma.sync.aligned.m16n8k8.row.col.f32.tf32.tf32.f32 "
                    "{%0,%1,%2,%3}, {%4,%5,%6,%7}, {%8,%9}, {%0,%1,%2,%3};"
                    : "+f"(acc[mt][nt][0]), "+f"(acc[mt][nt][1]),
                      "+f"(acc[mt][nt][2]), "+f"(acc[mt][nt][3])
                    : "r"(a[mt][0]), "r"(a[mt][1]), "r"(a[mt][2]), "r"(a[mt][3]),
                      "r"(b0), "r"(b1));
            }
        }
    }

    // transform in place (u stays in registers), accumulate local sum.
    // Diagonal tiles (8/64) take the q==s select; others skip it entirely.
    float local = 0.f;
    if (qbase == sbase) {
#pragma unroll
        for (int mt = 0; mt < 2; mt++) {
            int r0 = mrow + mt * 16 + g;
#pragma unroll
            for (int nt = 0; nt < 8; nt++) {
                int c = ncol + nt * 8 + tr * 2;
                float u0 = uexp(acc[mt][nt][0]); if (r0     == c    ) u0 = 0.f;
                float u1 = uexp(acc[mt][nt][1]); if (r0     == c + 1) u1 = 0.f;
                float u2 = uexp(acc[mt][nt][2]); if (r0 + 8 == c    ) u2 = 0.f;
                float u3 = uexp(acc[mt][nt][3]); if (r0 + 8 == c + 1) u3 = 0.f;
                acc[mt][nt][0] = u0; acc[mt][nt][1] = u1;
                acc[mt][nt][2] = u2; acc[mt][nt][3] = u3;
                local += (u0 + u1) + (u2 + u3);
            }
        }
    } else {
#pragma unroll
        for (int mt = 0; mt < 2; mt++)
#pragma unroll
            for (int nt = 0; nt < 8; nt++) {
                float u0 = uexp(acc[mt][nt][0]);
                float u1 = uexp(acc[mt][nt][1]);
                float u2 = uexp(acc[mt][nt][2]);
                float u3 = uexp(acc[mt][nt][3]);
                acc[mt][nt][0] = u0; acc[mt][nt][1] = u1;
                acc[mt][nt][2] = u2; acc[mt][nt][3] = u3;
                local += (u0 + u1) + (u2 + u3);
            }
    }
    // block reduce -> one atomicAdd + arrival count; spin until batch done
#pragma unroll
    for (int o = 16; o; o >>= 1)
        local += __shfl_down_sync(0xffffffffu, local, o);
    if (lane == 0) swarp[warp] = local;
    __syncthreads();
    if (tid == 0) {
        float tot = swarp[0];
#pragma unroll
        for (int w = 1; w < 8; w++) tot += swarp[w];
        atomicAdd(&g_Z[bz], tot);
        __threadfence();
        atomicAdd(&g_cnt[bz], 1);
        volatile int* vc = g_cnt;
        while (vc[bz] < 64) { }
        volatile float* vz = g_Z;
        sinv = 1.0f / vz[bz];
    }
    __syncthreads();
    const float inv = sinv;

    // single normalized write
    float* orow = out + ((size_t)bz << 20);
#pragma unroll
    for (int mt = 0; mt < 2; mt++) {
        int r0 = qbase + mrow + mt * 16 + g;
#pragma unroll
        for (int nt = 0; nt < 8; nt++) {
            int c = sbase + ncol + nt * 8 + tr * 2;
            *(float2*)(orow + (size_t)r0 * SS + c) =
                make_float2(acc[mt][nt][0] * inv, acc[mt][nt][1] * inv);
            *(float2*)(orow + (size_t)(r0 + 8) * SS + c) =
                make_float2(acc[mt][nt][2] * inv, acc[mt][nt][3] * inv);
        }
    }
}

// ---------------------------------------------------------------------------
extern "C" void kernel_launch(void* const* d_in, const int* in_sizes, int n_in,
                              void* d_out, int out_size)
{
    const float* q  = (const float*)d_in[0];   // query [48,1024,128]
    const float* wq = (const float*)d_in[3];   // W_query [128,64]
    const float* wk = (const float*)d_in[4];   // W_key   [128,64]
    float* out = (float*)d_out;                // [48, 1024*1024] fp32

    cudaFuncSetAttribute(proj_kernel,
                         cudaFuncAttributeMaxDynamicSharedMemorySize, PROJ_SMEM);
    cudaFuncSetAttribute(score_kernel,
                         cudaFuncAttributeMaxDynamicSharedMemorySize, SCORE_SMEM);

    proj_kernel<<<384, 256, PROJ_SMEM>>>(q, wq, wk);
    score_kernel<<<3072, 256, SCORE_SMEM>>>(out);
}

// round 12
// speedup vs baseline: 1.1070x; 1.1070x over previous
#include <cuda_runtime.h>
#include <math.h>
#include <stdint.h>

#define NB 48
#define SS 1024
#define DD 128
#define DKK 64
#define WSTRIDE 136   // [k][n] W row stride in words: >=128 and ==8 (mod 32)

// scratch (static device globals: allocation-free per harness rules)
__device__ float g_Q[NB * SS * DKK];   // tf32-rounded projections
__device__ float g_K[NB * SS * DKK];
__device__ float g_Z[NB];
__device__ int   g_cnt[NB];

__device__ __forceinline__ uint32_t f2tf32(float v) {
    uint32_t r;
    asm("cvt.rna.tf32.f32 %0, %1;" : "=r"(r) : "f"(v));
    return r;
}

// ---------------------------------------------------------------------------
// Kernel 1: fused Q|K projection, 2-term tf32: C = Ah*Wh + Ah*Wl.
// NO setup kernel: each CTA stages raw W per k-chunk in NATURAL [k][n] order
// (coalesced loads + contiguous STS.128), splitting hi/lo inline.
// W row stride = 136 words (>=128 to hold the row — the R11 bug was using a
// 40-word stride; 136 mod 32 = 8 keeps B-fragment LDS conflict-free:
// bank = (8*tr + g + const) mod 32 covers all 32 banks exactly once).
// Wh/Wl VALUES are identical to the pre-split path -> outputs bit-identical.
// Block 0 zeroes g_Z / g_cnt (kernel boundary orders it before score).
// Outputs tf32-rounded so score stages them as a pure cp.async byte copy.
// smem: sAh 128x36 + sWh/sWl 32x136 each = 53248 B.
// ---------------------------------------------------------------------------
#define PROJ_SMEM (128 * 36 * 4 + 2 * 32 * WSTRIDE * 4)

__global__ __launch_bounds__(256) void proj_kernel(
    const float* __restrict__ A,
    const float* __restrict__ Wq,
    const float* __restrict__ Wk)
{
    if (blockIdx.x == 0 && threadIdx.x < NB) {
        g_Z[threadIdx.x] = 0.f;
        g_cnt[threadIdx.x] = 0;
    }

    extern __shared__ uint32_t smem[];
    uint32_t* sAh = smem;                  // [128][36]
    uint32_t* sWh = sAh + 128 * 36;        // [k][n], stride WSTRIDE
    uint32_t* sWl = sWh + 32 * WSTRIDE;

    const int tid  = threadIdx.x;
    const int lane = tid & 31, warp = tid >> 5;
    const int rowbase = blockIdx.x * 128;

    const int mrow = (warp & 3) * 32;
    const int ncol = (warp >> 2) * 64;
    const int g  = lane >> 2;
    const int tr = lane & 3;

    float acc[2][8][4];
#pragma unroll
    for (int mt = 0; mt < 2; mt++)
#pragma unroll
        for (int nt = 0; nt < 8; nt++)
#pragma unroll
            for (int r = 0; r < 4; r++) acc[mt][nt][r] = 0.f;

    for (int k0 = 0; k0 < DD; k0 += 32) {
        // stage A chunk 128x32, tf32 hi only, STS.128 (row stride 144B)
#pragma unroll
        for (int it = 0; it < 4; it++) {
            int f = tid + 256 * it;
            int m = f >> 3, k4 = (f & 7) * 4;
            float4 v = *(const float4*)(A + (size_t)(rowbase + m) * DD + k0 + k4);
            uint4 h = make_uint4(f2tf32(v.x), f2tf32(v.y),
                                 f2tf32(v.z), f2tf32(v.w));
            *(uint4*)&sAh[m * 36 + k4] = h;
        }
        // stage raw W chunk [32k][128n] with inline hi/lo split (coalesced)
#pragma unroll
        for (int it = 0; it < 4; it++) {
            int f4 = tid + 256 * it;          // 1024 float4s: 32k x 32 n-quads
            int k  = f4 >> 5;                 // 0..31
            int n4 = (f4 & 31) * 4;           // 0..124
            float4 v = (n4 < 64)
                ? *(const float4*)(Wq + (size_t)(k0 + k) * DKK + n4)
                : *(const float4*)(Wk + (size_t)(k0 + k) * DKK + (n4 - 64));
            uint4 h = make_uint4(f2tf32(v.x), f2tf32(v.y),
                                 f2tf32(v.z), f2tf32(v.w));
            uint4 l = make_uint4(
                f2tf32(v.x - __uint_as_float(h.x)),
                f2tf32(v.y - __uint_as_float(h.y)),
                f2tf32(v.z - __uint_as_float(h.z)),
                f2tf32(v.w - __uint_as_float(h.w)));
            *(uint4*)&sWh[k * WSTRIDE + n4] = h;
            *(uint4*)&sWl[k * WSTRIDE + n4] = l;
        }
        __syncthreads();

#pragma unroll
        for (int kc = 0; kc < 4; kc++) {
            const int kk = kc * 8;
            uint32_t ah[2][4];
#pragma unroll
            for (int mt = 0; mt < 2; mt++) {
                int r = mrow + mt * 16 + g;
                ah[mt][0] = sAh[r * 36 + kk + tr];
                ah[mt][1] = sAh[(r + 8) * 36 + kk + tr];
                ah[mt][2] = sAh[r * 36 + kk + tr + 4];
                ah[mt][3] = sAh[(r + 8) * 36 + kk + tr + 4];
            }
#pragma unroll
            for (int nt = 0; nt < 8; nt++) {
                int c = ncol + nt * 8 + g;
                uint32_t bh0 = sWh[(kk + tr) * WSTRIDE + c];
                uint32_t bh1 = sWh[(kk + tr + 4) * WSTRIDE + c];
                uint32_t bl0 = sWl[(kk + tr) * WSTRIDE + c];
                uint32_t bl1 = sWl[(kk + tr + 4) * WSTRIDE + c];
#pragma unroll
                for (int mt = 0; mt < 2; mt++) {
                    asm volatile(
                        "mma.sync.aligned.m16n8k8.row.col.f32.tf32.tf32.f32 "
                        "{%0,%1,%2,%3}, {%4,%5,%6,%7}, {%8,%9}, {%0,%1,%2,%3};"
                        : "+f"(acc[mt][nt][0]), "+f"(acc[mt][nt][1]),
                          "+f"(acc[mt][nt][2]), "+f"(acc[mt][nt][3])
                        : "r"(ah[mt][0]), "r"(ah[mt][1]), "r"(ah[mt][2]), "r"(ah[mt][3]),
                          "r"(bh0), "r"(bh1));
                    asm volatile(
                        "mma.sync.aligned.m16n8k8.row.col.f32.tf32.tf32.f32 "
                        "{%0,%1,%2,%3}, {%4,%5,%6,%7}, {%8,%9}, {%0,%1,%2,%3};"
                        : "+f"(acc[mt][nt][0]), "+f"(acc[mt][nt][1]),
                          "+f"(acc[mt][nt][2]), "+f"(acc[mt][nt][3])
                        : "r"(ah[mt][0]), "r"(ah[mt][1]), "r"(ah[mt][2]), "r"(ah[mt][3]),
                          "r"(bl0), "r"(bl1));
                }
            }
        }
        __syncthreads();
    }

    // store tf32-ROUNDED outputs (score stages them as a raw copy)
#pragma unroll
    for (int mt = 0; mt < 2; mt++) {
        int m0 = rowbase + mrow + mt * 16 + g;
#pragma unroll
        for (int nt = 0; nt < 8; nt++) {
            int c = ncol + nt * 8 + tr * 2;
            float* dst = (c < 64) ? g_Q : g_K;
            int cc = c & 63;
            *(float2*)(dst + (size_t)m0 * DKK + cc) = make_float2(
                __uint_as_float(f2tf32(acc[mt][nt][0])),
                __uint_as_float(f2tf32(acc[mt][nt][1])));
            *(float2*)(dst + (size_t)(m0 + 8) * DKK + cc) = make_float2(
                __uint_as_float(f2tf32(acc[mt][nt][2])),
                __uint_as_float(f2tf32(acc[mt][nt][3])));
        }
    }
}

// ---------------------------------------------------------------------------
// Kernel 2: score tile + self-normalizing epilogue (R9-exact; uexp form
// verified bit-identical in R10).
// ---------------------------------------------------------------------------
#define SCORE_SMEM (2 * 128 * 68 * 4)

__device__ __forceinline__ float uexp(float x) {
    float t, r, u;
    asm("ex2.approx.f32 %0, %1;" : "=f"(t) : "f"(x * 2.8853900817779268f));
    asm("rcp.approx.f32 %0, %1;" : "=f"(r) : "f"(t + 1.0f));
    asm("ex2.approx.f32 %0, %1;" : "=f"(u) : "f"(r * -28.853900817779268f));
    return u;
}

__global__ __launch_bounds__(256, 3) void score_kernel(float* __restrict__ out)
{
    extern __shared__ uint32_t ssm[];
    uint32_t* sQ = ssm;                // [128][68]
    uint32_t* sK = ssm + 128 * 68;
    __shared__ float swarp[8];
    __shared__ float sinv;

    const int tid  = threadIdx.x;
    const int lane = tid & 31, warp = tid >> 5;
    const int bz    = blockIdx.x >> 6;
    const int tile  = blockIdx.x & 63;
    const int qbase = (tile >> 3) * 128;
    const int sbase = (tile & 7) * 128;

    const float* Qb = g_Q + (size_t)bz * SS * DKK + (size_t)qbase * DKK;
    const float* Kb = g_K + (size_t)bz * SS * DKK + (size_t)sbase * DKK;

    const int mrow = (warp & 3) * 32;
    const int ncol = (warp >> 2) * 64;
    const int g  = lane >> 2;
    const int tr = lane & 3;

    // stage full 128x64 Q and K tiles via cp.async (pure copy, MLP=16)
#pragma unroll
    for (int it = 0; it < 8; it++) {
        int f = tid + 256 * it;            // 0..2047
        int m = f >> 4, k4 = (f & 15) * 4;
        uint32_t dq = (uint32_t)__cvta_generic_to_shared(&sQ[m * 68 + k4]);
        asm volatile("cp.async.cg.shared.global [%0], [%1], 16;"
                     :: "r"(dq), "l"(Qb + m * DKK + k4));
        uint32_t dk = (uint32_t)__cvta_generic_to_shared(&sK[m * 68 + k4]);
        asm volatile("cp.async.cg.shared.global [%0], [%1], 16;"
                     :: "r"(dk), "l"(Kb + m * DKK + k4));
    }
    asm volatile("cp.async.commit_group;");

    float acc[2][8][4];
#pragma unroll
    for (int mt = 0; mt < 2; mt++)
#pragma unroll
        for (int nt = 0; nt < 8; nt++)
#pragma unroll
            for (int r = 0; r < 4; r++) acc[mt][nt][r] = 0.f;

    asm volatile("cp.async.wait_group 0;");
    __syncthreads();

#pragma unroll
    for (int kc = 0; kc < 8; kc++) {
        const int k0 = kc * 8;
        uint32_t a[2][4];
#pragma unroll
        for (int mt = 0; mt < 2; mt++) {
            int r = mrow + mt * 16 + g;
            a[mt][0] = sQ[r * 68 + k0 + tr];
            a[mt][1] = sQ[(r + 8) * 68 + k0 + tr];
            a[mt][2] = sQ[r * 68 + k0 + tr + 4];
            a[mt][3] = sQ[(r + 8) * 68 + k0 + tr + 4];
        }
#pragma unroll
        for (int nt = 0; nt < 8; nt++) {
            int c = ncol + nt * 8 + g;
            uint32_t b0 = sK[c * 68 + k0 + tr];
            uint32_t b1 = sK[c * 68 + k0 + tr + 4];
#pragma unroll
            for (int mt = 0; mt < 2; mt++) {
                asm volatile(
                    "mma.sync.aligned.m16n8k8.row.col.f32.tf32.tf32.f32 "
                    "{%0,%1,%2,%3}, {%4,%5,%6,%7}, {%8,%9}, {%0,%1,%2,%3};"
                    : "+f"(acc[mt][nt][0]), "+f"(acc[mt][nt][1]),
                      "+f"(acc[mt][nt][2]), "+f"(acc[mt][nt][3])
                    : "r"(a[mt][0]), "r"(a[mt][1]), "r"(a[mt][2]), "r"(a[mt][3]),
                      "r"(b0), "r"(b1));
            }
        }
    }

    // transform in place (u stays in registers), accumulate local sum.
    // Diagonal tiles (8/64) take the q==s select; others skip it entirely.
    float local = 0.f;
    if (qbase == sbase) {
#pragma unroll
        for (int mt = 0; mt < 2; mt++) {
            int r0 = mrow + mt * 16 + g;
#pragma unroll
            for (int nt = 0; nt < 8; nt++) {
                int c = ncol + nt * 8 + tr * 2;
                float u0 = uexp(acc[mt][nt][0]); if (r0     == c    ) u0 = 0.f;
                float u1 = uexp(acc[mt][nt][1]); if (r0     == c + 1) u1 = 0.f;
                float u2 = uexp(acc[mt][nt][2]); if (r0 + 8 == c    ) u2 = 0.f;
                float u3 = uexp(acc[mt][nt][3]); if (r0 + 8 == c + 1) u3 = 0.f;
                acc[mt][nt][0] = u0; acc[mt][nt][1] = u1;
                acc[mt][nt][2] = u2; acc[mt][nt][3] = u3;
                local += (u0 + u1) + (u2 + u3);
            }
        }
    } else {
#pragma unroll
        for (int mt = 0; mt < 2; mt++)
#pragma unroll
            for (int nt = 0; nt < 8; nt++) {
                float u0 = uexp(acc[mt][nt][0]);
                float u1 = uexp(acc[mt][nt][1]);
                float u2 = uexp(acc[mt][nt][2]);
                float u3 = uexp(acc[mt][nt][3]);
                acc[mt][nt][0] = u0; acc[mt][nt][1] = u1;
                acc[mt][nt][2] = u2; acc[mt][nt][3] = u3;
                local += (u0 + u1) + (u2 + u3);
            }
    }
    // block reduce -> one atomicAdd + arrival count; spin until batch done
#pragma unroll
    for (int o = 16; o; o >>= 1)
        local += __shfl_down_sync(0xffffffffu, local, o);
    if (lane == 0) swarp[warp] = local;
    __syncthreads();
    if (tid == 0) {
        float tot = swarp[0];
#pragma unroll
        for (int w = 1; w < 8; w++) tot += swarp[w];
        atomicAdd(&g_Z[bz], tot);
        __threadfence();
        atomicAdd(&g_cnt[bz], 1);
        volatile int* vc = g_cnt;
        while (vc[bz] < 64) { }
        volatile float* vz = g_Z;
        sinv = 1.0f / vz[bz];
    }
    __syncthreads();
    const float inv = sinv;

    // single normalized write
    float* orow = out + ((size_t)bz << 20);
#pragma unroll
    for (int mt = 0; mt < 2; mt++) {
        int r0 = qbase + mrow + mt * 16 + g;
#pragma unroll
        for (int nt = 0; nt < 8; nt++) {
            int c = sbase + ncol + nt * 8 + tr * 2;
            *(float2*)(orow + (size_t)r0 * SS + c) =
                make_float2(acc[mt][nt][0] * inv, acc[mt][nt][1] * inv);
            *(float2*)(orow + (size_t)(r0 + 8) * SS + c) =
                make_float2(acc[mt][nt][2] * inv, acc[mt][nt][3] * inv);
        }
    }
}

// ---------------------------------------------------------------------------
extern "C" void kernel_launch(void* const* d_in, const int* in_sizes, int n_in,
                              void* d_out, int out_size)
{
    const float* q  = (const float*)d_in[0];   // query [48,1024,128]
    const float* wq = (const float*)d_in[3];   // W_query [128,64]
    const float* wk = (const float*)d_in[4];   // W_key   [128,64]
    float* out = (float*)d_out;                // [48, 1024*1024] fp32

    cudaFuncSetAttribute(proj_kernel,
                         cudaFuncAttributeMaxDynamicSharedMemorySize, PROJ_SMEM);
    cudaFuncSetAttribute(score_kernel,
                         cudaFuncAttributeMaxDynamicSharedMemorySize, SCORE_SMEM);

    proj_kernel<<<384, 256, PROJ_SMEM>>>(q, wq, wk);
    score_kernel<<<3072, 256, SCORE_SMEM>>>(out);
}